// round 2
// baseline (speedup 1.0000x reference)
#include <cuda_runtime.h>

// Problem constants
#define B_  8
#define N_  1024
#define C_  1024
#define V_  256
#define NK  16        // harmonics 1..16 (k=0 contributes exactly 0 to the statistic)

// GEMM tile
#define BM  128
#define BN  64
#define BK  16
#define NCHUNK (C_/BK)   // 64
#define NRB (B_*N_/BM)   // 64 row-blocks
#define NCB (V_/BN)      // 4 col-blocks

// Exclusive per-rowblock partial sums: [rowblock][v][k*2 + {cos,sin}]
__device__ float g_part[NRB][V_][2*NK];
__device__ float g_stat[B_*V_];

__global__ __launch_bounds__(256, 2)
void fused_gemm_cf(const float* __restrict__ proj, const float* __restrict__ Amat)
{
    __shared__ float As[BK][BM+4];     // transposed: As[k][m]
    __shared__ float Bs[BK][BN+4];
    __shared__ float xs[BM][BN+1];

    const int tid  = threadIdx.x;
    const int rb   = blockIdx.x;       // 0..63  (row block: 128 rows, always within one b)
    const int cb   = blockIdx.y;       // 0..3   (col block: 64 v)
    const int row0 = rb * BM;
    const int col0 = cb * BN;

    const int ty = tid >> 4;           // 0..15
    const int tx = tid & 15;           // 0..15

    // ---- global load mapping ----
    // proj tile BMxBK = 512 float4, 2 per thread
    const int lin0 = tid;
    const int lin1 = tid + 256;
    const int ar0 = lin0 >> 2, ac0 = lin0 & 3;
    const int ar1 = lin1 >> 2, ac1 = lin1 & 3;
    const float* pA0 = proj + (size_t)(row0 + ar0) * C_ + ac0 * 4;
    const float* pA1 = proj + (size_t)(row0 + ar1) * C_ + ac1 * 4;
    // A tile BKxBN = 256 float4, 1 per thread
    const int br = tid >> 4, bc = tid & 15;
    const float* pB0 = Amat + (size_t)br * V_ + col0 + bc * 4;

    float acc[8][4];
    #pragma unroll
    for (int i = 0; i < 8; i++)
        #pragma unroll
        for (int j = 0; j < 4; j++) acc[i][j] = 0.0f;

    // prologue: load chunk 0
    float4 pa0 = *(const float4*)(pA0);
    float4 pa1 = *(const float4*)(pA1);
    float4 pb  = *(const float4*)(pB0);

    {
        As[ac0*4+0][ar0] = pa0.x; As[ac0*4+1][ar0] = pa0.y;
        As[ac0*4+2][ar0] = pa0.z; As[ac0*4+3][ar0] = pa0.w;
        As[ac1*4+0][ar1] = pa1.x; As[ac1*4+1][ar1] = pa1.y;
        As[ac1*4+2][ar1] = pa1.z; As[ac1*4+3][ar1] = pa1.w;
        *(float4*)&Bs[br][bc*4] = pb;
    }
    __syncthreads();

    for (int ch = 0; ch < NCHUNK; ch++) {
        float4 na0, na1, nb;
        if (ch + 1 < NCHUNK) {
            const int kc = (ch + 1) * BK;
            na0 = *(const float4*)(pA0 + kc);
            na1 = *(const float4*)(pA1 + kc);
            nb  = *(const float4*)(pB0 + (size_t)kc * V_);
        }

        #pragma unroll
        for (int kk = 0; kk < BK; kk++) {
            float4 a0 = *(const float4*)&As[kk][ty*8];
            float4 a1 = *(const float4*)&As[kk][ty*8+4];
            float4 b  = *(const float4*)&Bs[kk][tx*4];
            float av[8] = {a0.x,a0.y,a0.z,a0.w,a1.x,a1.y,a1.z,a1.w};
            float bv[4] = {b.x,b.y,b.z,b.w};
            #pragma unroll
            for (int i = 0; i < 8; i++)
                #pragma unroll
                for (int j = 0; j < 4; j++)
                    acc[i][j] = fmaf(av[i], bv[j], acc[i][j]);
        }
        __syncthreads();

        if (ch + 1 < NCHUNK) {
            As[ac0*4+0][ar0] = na0.x; As[ac0*4+1][ar0] = na0.y;
            As[ac0*4+2][ar0] = na0.z; As[ac0*4+3][ar0] = na0.w;
            As[ac1*4+0][ar1] = na1.x; As[ac1*4+1][ar1] = na1.y;
            As[ac1*4+2][ar1] = na1.z; As[ac1*4+3][ar1] = na1.w;
            *(float4*)&Bs[br][bc*4] = nb;
            __syncthreads();
        }
    }

    // stage x tile to shared for column-major trig phase
    #pragma unroll
    for (int i = 0; i < 8; i++)
        #pragma unroll
        for (int j = 0; j < 4; j++)
            xs[ty*8 + i][tx*4 + j] = acc[i][j];
    __syncthreads();

    // ---- phase 2: characteristic-function accumulation ----
    // col owner: 4 consecutive lanes share a column (shuffle-reducible)
    const int col = tid >> 2;      // 0..63
    const int q   = tid & 3;       // row quarter

    const float dt = 3.0f / 16.0f;
    float cacc[NK], sacc[NK];
    #pragma unroll
    for (int k = 0; k < NK; k++) { cacc[k] = 0.0f; sacc[k] = 0.0f; }

    #pragma unroll 4
    for (int i = 0; i < 32; i++) {
        float x = xs[q*32 + i][col];
        float s1, c1;
        __sincosf(x * dt, &s1, &c1);
        float tc = 2.0f * c1;
        float ckm = 1.0f, skm = 0.0f;
        float ck = c1, sk = s1;
        cacc[0] += c1; sacc[0] += s1;
        #pragma unroll
        for (int k = 1; k < NK; k++) {
            float cn = fmaf(tc, ck, -ckm);
            float sn = fmaf(tc, sk, -skm);
            ckm = ck; skm = sk; ck = cn; sk = sn;
            cacc[k] += cn; sacc[k] += sn;
        }
    }

    // reduce across the 4 lanes sharing this column
    #pragma unroll
    for (int k = 0; k < NK; k++) {
        cacc[k] += __shfl_xor_sync(0xffffffffu, cacc[k], 1);
        cacc[k] += __shfl_xor_sync(0xffffffffu, cacc[k], 2);
        sacc[k] += __shfl_xor_sync(0xffffffffu, sacc[k], 1);
        sacc[k] += __shfl_xor_sync(0xffffffffu, sacc[k], 2);
    }

    if (q == 0) {
        float4* dst = (float4*)&g_part[rb][col0 + col][0];
        #pragma unroll
        for (int m = 0; m < NK/2; m++)
            dst[m] = make_float4(cacc[2*m], sacc[2*m], cacc[2*m+1], sacc[2*m+1]);
    }
}

// Combine 8 row-block partials per (b,v), compute per-(b,v) statistic
__global__ void finalize1()
{
    const int g = blockIdx.x * 256 + threadIdx.x;   // 0..2047
    const int b = g >> 8;
    const int v = g & 255;

    float Cs[NK], Ss[NK];
    #pragma unroll
    for (int k = 0; k < NK; k++) { Cs[k] = 0.0f; Ss[k] = 0.0f; }

    #pragma unroll
    for (int j = 0; j < 8; j++) {
        const float4* p = (const float4*)&g_part[b*8 + j][v][0];
        #pragma unroll
        for (int m = 0; m < 8; m++) {
            float4 u = p[m];
            Cs[2*m]   += u.x; Ss[2*m]   += u.y;
            Cs[2*m+1] += u.z; Ss[2*m+1] += u.w;
        }
    }

    const float dt = 3.0f / 16.0f;
    const float invN = 1.0f / (float)N_;
    float stat = 0.0f;
    #pragma unroll
    for (int k = 0; k < NK; k++) {
        float t   = (float)(k + 1) * dt;
        float phi = expf(-0.5f * t * t);
        float w   = ((k == NK - 1) ? 1.0f : 2.0f) * dt * phi;
        float cm  = Cs[k] * invN;
        float sm  = Ss[k] * invN;
        float d   = cm - phi;
        stat += (d*d + sm*sm) * w;
    }
    g_stat[g] = stat * (float)N_;
}

__global__ void finalize2(float* out)
{
    __shared__ float sh[256];
    float s = 0.0f;
    for (int i = threadIdx.x; i < B_*V_; i += 256) s += g_stat[i];
    sh[threadIdx.x] = s;
    __syncthreads();
    for (int off = 128; off > 0; off >>= 1) {
        if (threadIdx.x < off) sh[threadIdx.x] += sh[threadIdx.x + off];
        __syncthreads();
    }
    if (threadIdx.x == 0) out[0] = sh[0] / (float)(B_*V_);
}

extern "C" void kernel_launch(void* const* d_in, const int* in_sizes, int n_in,
                              void* d_out, int out_size)
{
    const float* proj = (const float*)d_in[0];
    const float* Amat = (const float*)d_in[1];
    // disambiguate by element count (proj = 8M, A = 256K)
    if (n_in >= 2 && in_sizes[0] == C_*V_ && in_sizes[1] == B_*N_*C_) {
        const float* t = proj; proj = Amat; Amat = t;
    }

    dim3 grid(NRB, NCB);
    fused_gemm_cf<<<grid, 256>>>(proj, Amat);
    finalize1<<<B_*V_/256, 256>>>();
    finalize2<<<1, 256>>>((float*)d_out);
}

// round 4
// speedup vs baseline: 1.8934x; 1.8934x over previous
#include <cuda_runtime.h>
#include <cuda_bf16.h>
#include <cstdint>

// Problem constants
#define B_  8
#define N_  1024
#define C_  1024
#define V_  256
#define NK  16        // harmonics 1..16 (k=0 contributes exactly 0)

// Tiling
#define TM  128
#define TN  128
#define BK  64
#define NCHUNK (C_/BK)     // 16
#define NRB (B_*N_/TM)     // 64 row blocks
#define NCB (V_/TN)        // 2 col blocks

// Padded SMEM rows: 64 bf16 + 8 pad = 72 elems = 144 bytes (144 mod 128 = 16 -> conflict-free ldmatrix)
#define LDS_ROW 144
#define MAT_BYTES (128 * LDS_ROW)      // 18432 per matrix
#define OFF_AHI 0
#define OFF_ALO (MAT_BYTES)
#define OFF_BHI (2*MAT_BYTES)
#define OFF_BLO (3*MAT_BYTES)
#define STAGE_BYTES (4*MAT_BYTES)      // 73728
#define XS_LD 132
#define SMEM_DYN (2*STAGE_BYTES)       // 147456 (epilogue xs reuses this)

__device__ __nv_bfloat16 g_Bt_hi[(size_t)V_*C_];
__device__ __nv_bfloat16 g_Bt_lo[(size_t)V_*C_];
__device__ float g_part[NRB][V_][2*NK];
__device__ float g_stat[B_*V_];

// ---------------- helpers ----------------
__device__ __forceinline__ uint32_t smem_u32(const void* p) {
    uint32_t a;
    asm("{ .reg .u64 t; cvta.to.shared.u64 t, %1; cvt.u32.u64 %0, t; }" : "=r"(a) : "l"(p));
    return a;
}

__device__ __forceinline__ void ldsm4(uint32_t* r, uint32_t addr) {
    asm volatile("ldmatrix.sync.aligned.m8n8.x4.shared.b16 {%0,%1,%2,%3}, [%4];"
        : "=r"(r[0]), "=r"(r[1]), "=r"(r[2]), "=r"(r[3]) : "r"(addr));
}

__device__ __forceinline__ void mma_bf16(float* c, const uint32_t* a, const uint32_t* b) {
    asm volatile(
        "mma.sync.aligned.m16n8k16.row.col.f32.bf16.bf16.f32 "
        "{%0,%1,%2,%3}, {%4,%5,%6,%7}, {%8,%9}, {%0,%1,%2,%3};"
        : "+f"(c[0]), "+f"(c[1]), "+f"(c[2]), "+f"(c[3])
        : "r"(a[0]), "r"(a[1]), "r"(a[2]), "r"(a[3]), "r"(b[0]), "r"(b[1]));
}

// ---------------- prep kernel: transpose + bf16-split A (C,V) -> Bt (V,C) ----------------
__global__ void prep_B(const float* __restrict__ Amat)
{
    __shared__ float sh[32][33];
    const int c0 = blockIdx.x * 32, v0 = blockIdx.y * 32;
    const int tx = threadIdx.x, ty = threadIdx.y;   // 32 x 8
    #pragma unroll
    for (int j = 0; j < 4; j++)
        sh[ty + 8*j][tx] = Amat[(size_t)(c0 + ty + 8*j) * V_ + v0 + tx];
    __syncthreads();
    #pragma unroll
    for (int j = 0; j < 4; j++) {
        const int v = v0 + ty + 8*j, c = c0 + tx;
        float x = sh[tx][ty + 8*j];
        __nv_bfloat16 h = __float2bfloat16(x);
        g_Bt_hi[(size_t)v * C_ + c] = h;
        g_Bt_lo[(size_t)v * C_ + c] = __float2bfloat16(x - __bfloat162float(h));
    }
}

// ---------------- staging ----------------
__device__ __forceinline__ void load_A_regs(const float* __restrict__ proj, int row0, int ch, int t, float4* ar)
{
    const float* p = proj + (size_t)(row0 + (t >> 4)) * C_ + ch * BK + (t & 15) * 4;
    #pragma unroll
    for (int j = 0; j < 8; j++)
        ar[j] = *(const float4*)(p + (size_t)16 * j * C_);
}

__device__ __forceinline__ void store_A(char* stage, int t, const float4* ar)
{
    const int kb = (t & 15) * 8;   // byte offset of 4 bf16
    #pragma unroll
    for (int j = 0; j < 8; j++) {
        const int row = (t >> 4) + 16 * j;
        const int off = row * LDS_ROW + kb;
        float4 a = ar[j];
        __nv_bfloat162 h01 = __floats2bfloat162_rn(a.x, a.y);
        __nv_bfloat162 h23 = __floats2bfloat162_rn(a.z, a.w);
        float lx = a.x - __bfloat162float(h01.x);
        float ly = a.y - __bfloat162float(h01.y);
        float lz = a.z - __bfloat162float(h23.x);
        float lw = a.w - __bfloat162float(h23.y);
        __nv_bfloat162 l01 = __floats2bfloat162_rn(lx, ly);
        __nv_bfloat162 l23 = __floats2bfloat162_rn(lz, lw);
        *(uint2*)(stage + OFF_AHI + off) = make_uint2(*(uint32_t*)&h01, *(uint32_t*)&h23);
        *(uint2*)(stage + OFF_ALO + off) = make_uint2(*(uint32_t*)&l01, *(uint32_t*)&l23);
    }
}

__device__ __forceinline__ void load_B_regs(int col0, int ch, int t, uint4* bh, uint4* bl)
{
    #pragma unroll
    for (int j = 0; j < 4; j++) {
        const int i = t + 256 * j;        // uint4 index 0..1023
        const int row = i >> 3, kq = i & 7;
        const size_t g = (size_t)(col0 + row) * C_ + ch * BK + kq * 8;
        bh[j] = *(const uint4*)(g_Bt_hi + g);
        bl[j] = *(const uint4*)(g_Bt_lo + g);
    }
}

__device__ __forceinline__ void store_B(char* stage, int t, const uint4* bh, const uint4* bl)
{
    #pragma unroll
    for (int j = 0; j < 4; j++) {
        const int i = t + 256 * j;
        const int row = i >> 3, kq = i & 7;
        const int off = row * LDS_ROW + kq * 16;
        *(uint4*)(stage + OFF_BHI + off) = bh[j];
        *(uint4*)(stage + OFF_BLO + off) = bl[j];
    }
}

// ---------------- main fused kernel ----------------
__global__ void __launch_bounds__(256, 1) gemm_cf_tc(const float* __restrict__ proj)
{
    extern __shared__ char smem[];
    const uint32_t sbase = smem_u32(smem);

    const int tid  = threadIdx.x;
    const int wid  = tid >> 5;
    const int lane = tid & 31;
    const int rb   = blockIdx.x;            // 0..63
    const int cb   = blockIdx.y;            // 0..1
    const int row0 = rb * TM;
    const int col0 = cb * TN;

    // warp tile: 2 (M) x 4 (N)
    const int wm0 = (wid >> 2) * 64;
    const int wn0 = (wid & 3) * 32;

    // per-lane ldmatrix address components
    const int sub = lane >> 3, r8 = lane & 7;
    const int a_m = r8 + (sub & 1) * 8;      // + wm0 + mt*16
    const int a_k = (sub >> 1) * 8;          // + k0
    const int b_n = r8 + (sub >> 1) * 8;     // + wn0 + ng*16
    const int b_k = (sub & 1) * 8;           // + k0

    float acc[4][4][4];
    #pragma unroll
    for (int mt = 0; mt < 4; mt++)
        #pragma unroll
        for (int nt = 0; nt < 4; nt++)
            #pragma unroll
            for (int j = 0; j < 4; j++) acc[mt][nt][j] = 0.0f;

    float4 ar[8]; uint4 brh[4], brl[4];

    // prologue: fill stage 0
    load_A_regs(proj, row0, 0, tid, ar);
    load_B_regs(col0, 0, tid, brh, brl);
    store_A(smem, tid, ar);
    store_B(smem, tid, brh, brl);
    __syncthreads();

    for (int ch = 0; ch < NCHUNK; ch++) {
        char* stage = smem + (ch & 1) * STAGE_BYTES;
        const uint32_t sg = sbase + (ch & 1) * STAGE_BYTES;

        if (ch + 1 < NCHUNK) {
            load_A_regs(proj, row0, ch + 1, tid, ar);
            load_B_regs(col0, ch + 1, tid, brh, brl);
        }

        // compute on this stage
        #pragma unroll
        for (int ks = 0; ks < 4; ks++) {
            const int k0 = ks * 16;
            // B fragments: [nt][2] for hi and lo
            uint32_t fbh[4][2], fbl[4][2];
            #pragma unroll
            for (int ng = 0; ng < 2; ng++) {
                uint32_t tmp[4];
                const uint32_t baddr = sg + (uint32_t)((wn0 + ng*16 + b_n) * LDS_ROW + (k0 + b_k) * 2);
                ldsm4(tmp, baddr + OFF_BHI);
                fbh[2*ng][0] = tmp[0]; fbh[2*ng][1] = tmp[1];
                fbh[2*ng+1][0] = tmp[2]; fbh[2*ng+1][1] = tmp[3];
                ldsm4(tmp, baddr + OFF_BLO);
                fbl[2*ng][0] = tmp[0]; fbl[2*ng][1] = tmp[1];
                fbl[2*ng+1][0] = tmp[2]; fbl[2*ng+1][1] = tmp[3];
            }
            #pragma unroll
            for (int mt = 0; mt < 4; mt++) {
                uint32_t fah[4], fal[4];
                const uint32_t aaddr = sg + (uint32_t)((wm0 + mt*16 + a_m) * LDS_ROW + (k0 + a_k) * 2);
                ldsm4(fah, aaddr + OFF_AHI);
                ldsm4(fal, aaddr + OFF_ALO);
                #pragma unroll
                for (int nt = 0; nt < 4; nt++) {
                    mma_bf16(acc[mt][nt], fah, fbh[nt]);
                    mma_bf16(acc[mt][nt], fah, fbl[nt]);
                    mma_bf16(acc[mt][nt], fal, fbh[nt]);
                }
            }
        }
        __syncthreads();

        if (ch + 1 < NCHUNK) {
            char* nxt = smem + ((ch + 1) & 1) * STAGE_BYTES;
            store_A(nxt, tid, ar);
            store_B(nxt, tid, brh, brl);
            __syncthreads();
        }
    }

    // ---- epilogue: accumulators -> xs[128][XS_LD] ----
    float* xs = (float*)smem;
    {
        const int mrow = lane >> 2;
        const int ncol = 2 * (lane & 3);
        #pragma unroll
        for (int mt = 0; mt < 4; mt++)
            #pragma unroll
            for (int nt = 0; nt < 4; nt++) {
                const int m = wm0 + mt*16 + mrow;
                const int n = wn0 + nt*8 + ncol;
                *(float2*)&xs[(size_t)m * XS_LD + n]       = make_float2(acc[mt][nt][0], acc[mt][nt][1]);
                *(float2*)&xs[(size_t)(m + 8) * XS_LD + n] = make_float2(acc[mt][nt][2], acc[mt][nt][3]);
            }
    }
    __syncthreads();

    // ---- trig phase: 2 lanes per column, 64 rows each ----
    const int col  = tid >> 1;        // 0..127
    const int half = tid & 1;
    const float dt = 3.0f / 16.0f;
    float cacc[NK], sacc[NK];
    #pragma unroll
    for (int k = 0; k < NK; k++) { cacc[k] = 0.0f; sacc[k] = 0.0f; }

    #pragma unroll 4
    for (int i = 0; i < 64; i++) {
        float x = xs[(size_t)(half * 64 + i) * XS_LD + col];
        float s1, c1;
        __sincosf(x * dt, &s1, &c1);
        float tc = 2.0f * c1;
        float ckm = 1.0f, skm = 0.0f;
        float ck = c1, sk = s1;
        cacc[0] += c1; sacc[0] += s1;
        #pragma unroll
        for (int k = 1; k < NK; k++) {
            float cn = fmaf(tc, ck, -ckm);
            float sn = fmaf(tc, sk, -skm);
            ckm = ck; skm = sk; ck = cn; sk = sn;
            cacc[k] += cn; sacc[k] += sn;
        }
    }
    #pragma unroll
    for (int k = 0; k < NK; k++) {
        cacc[k] += __shfl_xor_sync(0xffffffffu, cacc[k], 1);
        sacc[k] += __shfl_xor_sync(0xffffffffu, sacc[k], 1);
    }
    if (half == 0) {
        float4* dst = (float4*)&g_part[rb][col0 + col][0];
        #pragma unroll
        for (int m = 0; m < NK / 2; m++)
            dst[m] = make_float4(cacc[2*m], sacc[2*m], cacc[2*m+1], sacc[2*m+1]);
    }
}

// ---------------- finalize ----------------
__global__ void finalize1()
{
    const int g = blockIdx.x * 256 + threadIdx.x;   // 0..2047
    const int b = g >> 8;
    const int v = g & 255;

    float Cs[NK], Ss[NK];
    #pragma unroll
    for (int k = 0; k < NK; k++) { Cs[k] = 0.0f; Ss[k] = 0.0f; }

    #pragma unroll
    for (int j = 0; j < 8; j++) {
        const float4* p = (const float4*)&g_part[b*8 + j][v][0];
        #pragma unroll
        for (int m = 0; m < 8; m++) {
            float4 u = p[m];
            Cs[2*m]   += u.x; Ss[2*m]   += u.y;
            Cs[2*m+1] += u.z; Ss[2*m+1] += u.w;
        }
    }

    const float dt = 3.0f / 16.0f;
    const float invN = 1.0f / (float)N_;
    float stat = 0.0f;
    #pragma unroll
    for (int k = 0; k < NK; k++) {
        float t   = (float)(k + 1) * dt;
        float phi = expf(-0.5f * t * t);
        float w   = ((k == NK - 1) ? 1.0f : 2.0f) * dt * phi;
        float cm  = Cs[k] * invN;
        float sm  = Ss[k] * invN;
        float d   = cm - phi;
        stat += (d*d + sm*sm) * w;
    }
    g_stat[g] = stat * (float)N_;
}

__global__ void finalize2(float* out)
{
    __shared__ float sh[256];
    float s = 0.0f;
    for (int i = threadIdx.x; i < B_*V_; i += 256) s += g_stat[i];
    sh[threadIdx.x] = s;
    __syncthreads();
    for (int off = 128; off > 0; off >>= 1) {
        if (threadIdx.x < off) sh[threadIdx.x] += sh[threadIdx.x + off];
        __syncthreads();
    }
    if (threadIdx.x == 0) out[0] = sh[0] / (float)(B_*V_);
}

extern "C" void kernel_launch(void* const* d_in, const int* in_sizes, int n_in,
                              void* d_out, int out_size)
{
    const float* proj = (const float*)d_in[0];
    const float* Amat = (const float*)d_in[1];
    if (n_in >= 2 && in_sizes[0] == C_*V_ && in_sizes[1] == B_*N_*C_) {
        const float* t = proj; proj = Amat; Amat = t;
    }

    static int configured = 0;
    if (!configured) {
        cudaFuncSetAttribute(gemm_cf_tc, cudaFuncAttributeMaxDynamicSharedMemorySize, SMEM_DYN);
        configured = 1;
    }

    prep_B<<<dim3(C_/32, V_/32), dim3(32, 8)>>>(Amat);
    gemm_cf_tc<<<dim3(NRB, NCB), 256, SMEM_DYN>>>(proj);
    finalize1<<<B_*V_/256, 256>>>();
    finalize2<<<1, 256>>>((float*)d_out);
}

// round 6
// speedup vs baseline: 1.9077x; 1.0076x over previous
#include <cuda_runtime.h>
#include <cuda_bf16.h>
#include <cstdint>

// Problem constants
#define B_  8
#define N_  1024
#define C_  1024
#define V_  256
#define NK  16        // harmonics 1..16 (k=0 contributes exactly 0)

// Tiling
#define TM  128
#define TN  128
#define BK  64
#define NCHUNK (C_/BK)     // 16
#define NRB (B_*N_/TM)     // 64 row blocks
#define NCB (V_/TN)        // 2 col blocks

// Padded SMEM rows: 64 bf16 + 8 pad = 72 elems = 144 bytes (conflict-free ldmatrix)
#define LDS_ROW 144
#define MAT_BYTES (128 * LDS_ROW)      // 18432 per matrix
#define OFF_AHI 0
#define OFF_ALO (MAT_BYTES)
#define OFF_BHI (2*MAT_BYTES)
#define OFF_BLO (3*MAT_BYTES)
#define STAGE_BYTES (4*MAT_BYTES)      // 73728
#define XS_LD 132
#define SMEM_DYN (2*STAGE_BYTES)       // 147456 (epilogue xs reuses this)

__device__ __nv_bfloat16 g_Bt_hi[(size_t)V_*C_];
__device__ __nv_bfloat16 g_Bt_lo[(size_t)V_*C_];
__device__ float g_part[NRB][V_][2*NK];
__device__ float g_bsum[B_];

// ---------------- helpers ----------------
__device__ __forceinline__ uint32_t smem_u32(const void* p) {
    uint32_t a;
    asm("{ .reg .u64 t; cvta.to.shared.u64 t, %1; cvt.u32.u64 %0, t; }" : "=r"(a) : "l"(p));
    return a;
}

__device__ __forceinline__ void ldsm4(uint32_t* r, uint32_t addr) {
    asm volatile("ldmatrix.sync.aligned.m8n8.x4.shared.b16 {%0,%1,%2,%3}, [%4];"
        : "=r"(r[0]), "=r"(r[1]), "=r"(r[2]), "=r"(r[3]) : "r"(addr));
}

__device__ __forceinline__ void mma_bf16(float* c, const uint32_t* a, const uint32_t* b) {
    asm volatile(
        "mma.sync.aligned.m16n8k16.row.col.f32.bf16.bf16.f32 "
        "{%0,%1,%2,%3}, {%4,%5,%6,%7}, {%8,%9}, {%0,%1,%2,%3};"
        : "+f"(c[0]), "+f"(c[1]), "+f"(c[2]), "+f"(c[3])
        : "r"(a[0]), "r"(a[1]), "r"(a[2]), "r"(a[3]), "r"(b[0]), "r"(b[1]));
}

__device__ __forceinline__ void cp_async16(uint32_t dst, const void* src) {
    asm volatile("cp.async.cg.shared.global [%0], [%1], 16;" :: "r"(dst), "l"(src));
}
#define CP_COMMIT() asm volatile("cp.async.commit_group;" ::: "memory")
#define CP_WAIT0()  asm volatile("cp.async.wait_group 0;" ::: "memory")

// ---------------- prep kernel: transpose + bf16-split A (C,V) -> Bt (V,C) ----------------
__global__ void prep_B(const float* __restrict__ Amat)
{
    __shared__ float sh[32][33];
    const int c0 = blockIdx.x * 32, v0 = blockIdx.y * 32;
    const int tx = threadIdx.x, ty = threadIdx.y;   // 32 x 8
    #pragma unroll
    for (int j = 0; j < 4; j++)
        sh[ty + 8*j][tx] = Amat[(size_t)(c0 + ty + 8*j) * V_ + v0 + tx];
    __syncthreads();
    #pragma unroll
    for (int j = 0; j < 4; j++) {
        const int v = v0 + ty + 8*j, c = c0 + tx;
        float x = sh[tx][ty + 8*j];
        __nv_bfloat16 h = __float2bfloat16(x);
        g_Bt_hi[(size_t)v * C_ + c] = h;
        g_Bt_lo[(size_t)v * C_ + c] = __float2bfloat16(x - __bfloat162float(h));
    }
}

// ---------------- staging ----------------
__device__ __forceinline__ void load_A_regs(const float* __restrict__ proj, int row0, int ch, int t, float4* ar)
{
    const float* p = proj + (size_t)(row0 + (t >> 4)) * C_ + ch * BK + (t & 15) * 4;
    #pragma unroll
    for (int j = 0; j < 8; j++)
        ar[j] = *(const float4*)(p + (size_t)16 * j * C_);
}

__device__ __forceinline__ void store_A(char* stage, int t, const float4* ar)
{
    const int kb = (t & 15) * 8;   // byte offset of 4 bf16
    #pragma unroll
    for (int j = 0; j < 8; j++) {
        const int row = (t >> 4) + 16 * j;
        const int off = row * LDS_ROW + kb;
        float4 a = ar[j];
        __nv_bfloat162 h01 = __floats2bfloat162_rn(a.x, a.y);
        __nv_bfloat162 h23 = __floats2bfloat162_rn(a.z, a.w);
        float lx = a.x - __bfloat162float(h01.x);
        float ly = a.y - __bfloat162float(h01.y);
        float lz = a.z - __bfloat162float(h23.x);
        float lw = a.w - __bfloat162float(h23.y);
        __nv_bfloat162 l01 = __floats2bfloat162_rn(lx, ly);
        __nv_bfloat162 l23 = __floats2bfloat162_rn(lz, lw);
        *(uint2*)(stage + OFF_AHI + off) = make_uint2(*(uint32_t*)&h01, *(uint32_t*)&h23);
        *(uint2*)(stage + OFF_ALO + off) = make_uint2(*(uint32_t*)&l01, *(uint32_t*)&l23);
    }
}

// B staging via cp.async: gmem (pre-split bf16) -> smem directly
__device__ __forceinline__ void stage_B_async(uint32_t sg, int col0, int ch, int t)
{
    #pragma unroll
    for (int j = 0; j < 4; j++) {
        const int i = t + 256 * j;        // 16B segment index 0..1023
        const int row = i >> 3, kq = i & 7;
        const size_t g = (size_t)(col0 + row) * C_ + ch * BK + kq * 8;
        const uint32_t off = (uint32_t)(row * LDS_ROW + kq * 16);
        cp_async16(sg + OFF_BHI + off, g_Bt_hi + g);
        cp_async16(sg + OFF_BLO + off, g_Bt_lo + g);
    }
    CP_COMMIT();
}

// ---------------- main fused kernel ----------------
__global__ void __launch_bounds__(256, 1) gemm_cf_tc(const float* __restrict__ proj)
{
    extern __shared__ char smem[];
    const uint32_t sbase = smem_u32(smem);

    const int tid  = threadIdx.x;
    const int wid  = tid >> 5;
    const int lane = tid & 31;
    const int rb   = blockIdx.x;            // 0..63
    const int cb   = blockIdx.y;            // 0..1
    const int row0 = rb * TM;
    const int col0 = cb * TN;

    // warp tile: 2 (M) x 4 (N)
    const int wm0 = (wid >> 2) * 64;
    const int wn0 = (wid & 3) * 32;

    // per-lane ldmatrix address components
    const int sub = lane >> 3, r8 = lane & 7;
    const int a_m = r8 + (sub & 1) * 8;
    const int a_k = (sub >> 1) * 8;
    const int b_n = r8 + (sub >> 1) * 8;
    const int b_k = (sub & 1) * 8;

    float acc[4][4][4];
    #pragma unroll
    for (int mt = 0; mt < 4; mt++)
        #pragma unroll
        for (int nt = 0; nt < 4; nt++)
            #pragma unroll
            for (int j = 0; j < 4; j++) acc[mt][nt][j] = 0.0f;

    float4 ar[8];

    // prologue: fill stage 0
    stage_B_async(sbase, col0, 0, tid);
    load_A_regs(proj, row0, 0, tid, ar);
    store_A(smem, tid, ar);
    CP_WAIT0();
    __syncthreads();

    for (int ch = 0; ch < NCHUNK; ch++) {
        const uint32_t sg = sbase + (ch & 1) * STAGE_BYTES;
        const uint32_t sn = sbase + ((ch + 1) & 1) * STAGE_BYTES;
        char* nxt = smem + ((ch + 1) & 1) * STAGE_BYTES;

        if (ch + 1 < NCHUNK) {
            stage_B_async(sn, col0, ch + 1, tid);          // async B fill of next buffer
            load_A_regs(proj, row0, ch + 1, tid, ar);      // A LDGs in flight during compute
        }

        // compute on current stage
        #pragma unroll
        for (int ks = 0; ks < 4; ks++) {
            const int k0 = ks * 16;
            uint32_t fbh[4][2], fbl[4][2];
            #pragma unroll
            for (int ng = 0; ng < 2; ng++) {
                uint32_t tmp[4];
                const uint32_t baddr = sg + (uint32_t)((wn0 + ng*16 + b_n) * LDS_ROW + (k0 + b_k) * 2);
                ldsm4(tmp, baddr + OFF_BHI);
                fbh[2*ng][0] = tmp[0]; fbh[2*ng][1] = tmp[1];
                fbh[2*ng+1][0] = tmp[2]; fbh[2*ng+1][1] = tmp[3];
                ldsm4(tmp, baddr + OFF_BLO);
                fbl[2*ng][0] = tmp[0]; fbl[2*ng][1] = tmp[1];
                fbl[2*ng+1][0] = tmp[2]; fbl[2*ng+1][1] = tmp[3];
            }
            #pragma unroll
            for (int mt = 0; mt < 4; mt++) {
                uint32_t fah[4], fal[4];
                const uint32_t aaddr = sg + (uint32_t)((wm0 + mt*16 + a_m) * LDS_ROW + (k0 + a_k) * 2);
                ldsm4(fah, aaddr + OFF_AHI);
                ldsm4(fal, aaddr + OFF_ALO);
                #pragma unroll
                for (int nt = 0; nt < 4; nt++) {
                    mma_bf16(acc[mt][nt], fah, fbh[nt]);
                    mma_bf16(acc[mt][nt], fah, fbl[nt]);
                    mma_bf16(acc[mt][nt], fal, fbh[nt]);
                }
            }
        }

        if (ch + 1 < NCHUNK) {
            store_A(nxt, tid, ar);   // writes next buffer; its last readers all passed previous barrier
        }
        CP_WAIT0();
        __syncthreads();             // single barrier per chunk
    }

    // ---- epilogue: accumulators -> xs[128][XS_LD] ----
    float* xs = (float*)smem;
    {
        const int mrow = lane >> 2;
        const int ncol = 2 * (lane & 3);
        #pragma unroll
        for (int mt = 0; mt < 4; mt++)
            #pragma unroll
            for (int nt = 0; nt < 4; nt++) {
                const int m = wm0 + mt*16 + mrow;
                const int n = wn0 + nt*8 + ncol;
                *(float2*)&xs[(size_t)m * XS_LD + n]       = make_float2(acc[mt][nt][0], acc[mt][nt][1]);
                *(float2*)&xs[(size_t)(m + 8) * XS_LD + n] = make_float2(acc[mt][nt][2], acc[mt][nt][3]);
            }
    }
    __syncthreads();

    // ---- trig phase: 2 lanes per column, 64 rows each ----
    const int col  = tid >> 1;        // 0..127
    const int half = tid & 1;
    const float dt = 3.0f / 16.0f;
    float cacc[NK], sacc[NK];
    #pragma unroll
    for (int k = 0; k < NK; k++) { cacc[k] = 0.0f; sacc[k] = 0.0f; }

    #pragma unroll 4
    for (int i = 0; i < 64; i++) {
        float x = xs[(size_t)(half * 64 + i) * XS_LD + col];
        float s1, c1;
        __sincosf(x * dt, &s1, &c1);
        float tc = 2.0f * c1;
        float ckm = 1.0f, skm = 0.0f;
        float ck = c1, sk = s1;
        cacc[0] += c1; sacc[0] += s1;
        #pragma unroll
        for (int k = 1; k < NK; k++) {
            float cn = fmaf(tc, ck, -ckm);
            float sn = fmaf(tc, sk, -skm);
            ckm = ck; skm = sk; ck = cn; sk = sn;
            cacc[k] += cn; sacc[k] += sn;
        }
    }
    #pragma unroll
    for (int k = 0; k < NK; k++) {
        cacc[k] += __shfl_xor_sync(0xffffffffu, cacc[k], 1);
        sacc[k] += __shfl_xor_sync(0xffffffffu, sacc[k], 1);
    }
    if (half == 0) {
        float4* dst = (float4*)&g_part[rb][col0 + col][0];
        #pragma unroll
        for (int m = 0; m < NK / 2; m++)
            dst[m] = make_float4(cacc[2*m], sacc[2*m], cacc[2*m+1], sacc[2*m+1]);
    }
}

// ---------------- finalize ----------------
// One block per b (8 blocks): per-thread (b,v) statistic, then block-reduce to g_bsum[b]
__global__ void finalize1()
{
    const int b = blockIdx.x;
    const int v = threadIdx.x;   // 0..255

    float Cs[NK], Ss[NK];
    #pragma unroll
    for (int k = 0; k < NK; k++) { Cs[k] = 0.0f; Ss[k] = 0.0f; }

    #pragma unroll
    for (int j = 0; j < 8; j++) {
        const float4* p = (const float4*)&g_part[b*8 + j][v][0];
        #pragma unroll
        for (int m = 0; m < 8; m++) {
            float4 u = p[m];
            Cs[2*m]   += u.x; Ss[2*m]   += u.y;
            Cs[2*m+1] += u.z; Ss[2*m+1] += u.w;
        }
    }

    const float dt = 3.0f / 16.0f;
    const float invN = 1.0f / (float)N_;
    float stat = 0.0f;
    #pragma unroll
    for (int k = 0; k < NK; k++) {
        float t   = (float)(k + 1) * dt;
        float phi = expf(-0.5f * t * t);
        float w   = ((k == NK - 1) ? 1.0f : 2.0f) * dt * phi;
        float cm  = Cs[k] * invN;
        float sm  = Ss[k] * invN;
        float d   = cm - phi;
        stat += (d*d + sm*sm) * w;
    }
    stat *= (float)N_;

    __shared__ float sh[256];
    sh[v] = stat;
    __syncthreads();
    #pragma unroll
    for (int off = 128; off > 0; off >>= 1) {
        if (v < off) sh[v] += sh[v + off];
        __syncthreads();
    }
    if (v == 0) g_bsum[b] = sh[0];
}

__global__ void finalize2(float* out)
{
    if (threadIdx.x == 0) {
        float s = 0.0f;
        #pragma unroll
        for (int b = 0; b < B_; b++) s += g_bsum[b];
        out[0] = s / (float)(B_*V_);
    }
}

extern "C" void kernel_launch(void* const* d_in, const int* in_sizes, int n_in,
                              void* d_out, int out_size)
{
    const float* proj = (const float*)d_in[0];
    const float* Amat = (const float*)d_in[1];
    if (n_in >= 2 && in_sizes[0] == C_*V_ && in_sizes[1] == B_*N_*C_) {
        const float* t = proj; proj = Amat; Amat = t;
    }

    // Unconditional (no static guards per harness rules); idempotent and cheap.
    cudaFuncSetAttribute(gemm_cf_tc, cudaFuncAttributeMaxDynamicSharedMemorySize, SMEM_DYN);

    prep_B<<<dim3(C_/32, V_/32), dim3(32, 8)>>>(Amat);
    gemm_cf_tc<<<dim3(NRB, NCB), 256, SMEM_DYN>>>(proj);
    finalize1<<<B_, 256>>>();
    finalize2<<<1, 32>>>((float*)d_out);
}